// round 15
// baseline (speedup 1.0000x reference)
#include <cuda_runtime.h>
#include <cuda_fp16.h>
#include <cstdint>

#define BATCH 256
#define NTOK  320
#define CDIM  768
#define LZ    64
#define LK    256
#define SCALE 0.125f

__device__ __half g_Xh[(size_t)BATCH * NTOK * CDIM];   // fp16 copy of x
__device__ __half g_Wh[(size_t)CDIM * CDIM];           // fp16 copy of proj_w
__device__ __half g_OTh[(size_t)BATCH * CDIM * LZ];    // O^T fp16; flat == Y_all(16384x768)

__device__ __forceinline__ void mma16(float* d, const uint32_t* a,
                                      uint32_t b0, uint32_t b1) {
    asm volatile(
        "mma.sync.aligned.m16n8k16.row.col.f32.f16.f16.f32 "
        "{%0,%1,%2,%3}, {%4,%5,%6,%7}, {%8,%9}, {%0,%1,%2,%3};\n"
        : "+f"(d[0]), "+f"(d[1]), "+f"(d[2]), "+f"(d[3])
        : "r"(a[0]), "r"(a[1]), "r"(a[2]), "r"(a[3]), "r"(b0), "r"(b1));
}
__device__ __forceinline__ void ldsm4(uint32_t* r, uint32_t saddr) {
    asm volatile("ldmatrix.sync.aligned.m8n8.x4.shared.b16 {%0,%1,%2,%3}, [%4];"
                 : "=r"(r[0]), "=r"(r[1]), "=r"(r[2]), "=r"(r[3]) : "r"(saddr));
}
__device__ __forceinline__ void ldsm4t(uint32_t* r, uint32_t saddr) {
    asm volatile("ldmatrix.sync.aligned.m8n8.x4.trans.shared.b16 {%0,%1,%2,%3}, [%4];"
                 : "=r"(r[0]), "=r"(r[1]), "=r"(r[2]), "=r"(r[3]) : "r"(saddr));
}
__device__ __forceinline__ void cpa16(uint32_t saddr, const void* gaddr) {
    asm volatile("cp.async.cg.shared.global [%0], [%1], 16;\n"
                 :: "r"(saddr), "l"(gaddr));
}
__device__ __forceinline__ void cpa_commit() {
    asm volatile("cp.async.commit_group;\n");
}
template <int N>
__device__ __forceinline__ void cpa_wait() {
    asm volatile("cp.async.wait_group %0;\n" :: "n"(N));
}

__device__ __forceinline__ uint2 f4h(float4 v) {
    __half2 a = __floats2half2_rn(v.x, v.y);
    __half2 b = __floats2half2_rn(v.z, v.w);
    uint2 r;
    r.x = *(uint32_t*)&a;
    r.y = *(uint32_t*)&b;
    return r;
}

// ---------------- convert pass: x->fp16, W->fp16 (no tail) ----------------
__global__ void conv_k(const float4* __restrict__ x4, const float4* __restrict__ w4) {
    const int WCH = CDIM * CDIM / 4;
    const int XCH = BATCH * NTOK * CDIM / 4;
    uint2* xh2 = (uint2*)g_Xh;
    uint2* wh2 = (uint2*)g_Wh;
    for (long i = blockIdx.x * blockDim.x + threadIdx.x; i < WCH + XCH;
         i += (long)gridDim.x * blockDim.x) {
        if (i < WCH) {
            wh2[i] = f4h(w4[i]);
        } else {
            long j = i - WCH;
            xh2[j] = f4h(x4[j]);
        }
    }
}

// ---------------- concat-tail copy (runs on forked stream) ----------------
__global__ void copy_tail(const float4* __restrict__ x4, float4* __restrict__ o4) {
    const int perB  = (LK * CDIM) / 4;      // 49152
    const int total = BATCH * perB;
    for (int i = blockIdx.x * blockDim.x + threadIdx.x; i < total;
         i += gridDim.x * blockDim.x) {
        int b = i / perB;
        int r = i - b * perB;
        int off = b * (NTOK * CDIM / 4) + (LZ * CDIM / 4) + r;
        o4[off] = x4[off];
    }
}

// ---------------- fused attention per batch (fp16 tensor cores) ----------------
#define P1_LDH 40    // halves; 80B row => conflict-free ldsm
#define SS_LD  260   // fp32 words
#define PS_LDH 264   // halves
#define K2_LDH 72    // halves; 144B row => conflict-free ldsm4t
#define STG_LD 68    // fp32 words

#define AT_SMEM 100608

extern __shared__ char smemc[];

__global__ __launch_bounds__(256, 2) void attn_k() {
    float*  sS = (float*)(smemc + 34048);
    __half* sP = (__half*)smemc;
    float*  stage = (float*)(smemc + 73728);
    uint32_t sb;
    asm("{ .reg .u64 t; cvta.to.shared.u64 t, %1; cvt.u32.u64 %0, t; }"
        : "=r"(sb) : "l"(smemc));

    const int b    = blockIdx.x;
    const int tid  = threadIdx.x;
    const int wid  = tid >> 5;
    const int lane = tid & 31;
    const int grp  = lane >> 2;
    const int qd   = lane & 3;
    const __half* xhb = g_Xh + (size_t)b * NTOK * CDIM;
    const __half* xhK = xhb + LZ * CDIM;

    const int lrow  = lane & 15;
    const int lcolh = (lane >> 4) * 8;
    const int brow  = (lane & 7) + ((lane >> 4) << 3);
    const int bcolh = ((lane >> 3) & 1) * 8;

    // ---------- Phase 1: S = Q K^T * scale ----------
    const int warp_m = wid >> 2;
    const int warp_n = wid & 3;

    float acc[2][8][4];
#pragma unroll
    for (int i = 0; i < 2; ++i)
#pragma unroll
        for (int j = 0; j < 8; ++j)
#pragma unroll
            for (int r = 0; r < 4; ++r) acc[i][j][r] = 0.0f;

    auto load_tiles = [&](int it, int st) {
        int c0 = it * 32;
        uint32_t qb = sb + st * 25600;
        uint32_t kb = qb + 5120;
        {
            int row = tid >> 2, kc = (tid & 3) * 8;
            cpa16(qb + row * 80 + kc * 2, xhb + row * CDIM + c0 + kc);
        }
#pragma unroll
        for (int p = 0; p < 4; ++p) {
            int id = p * 256 + tid;
            int row = id >> 2, kc = (id & 3) * 8;
            cpa16(kb + row * 80 + kc * 2, xhK + row * CDIM + c0 + kc);
        }
        cpa_commit();
    };

    load_tiles(0, 0);
    for (int it = 0; it < 24; ++it) {
        cpa_wait<0>();
        __syncthreads();
        if (it + 1 < 24) load_tiles(it + 1, (it + 1) & 1);

        uint32_t qb = sb + (it & 1) * 25600;
        uint32_t kb = qb + 5120;
#pragma unroll
        for (int s = 0; s < 2; ++s) {
            uint32_t a[2][4], bf[4][4];
            ldsm4(a[0], qb + ((warp_m * 32 + lrow) * P1_LDH + s * 16 + lcolh) * 2);
            ldsm4(a[1], qb + ((warp_m * 32 + 16 + lrow) * P1_LDH + s * 16 + lcolh) * 2);
#pragma unroll
            for (int nt2 = 0; nt2 < 4; ++nt2)
                ldsm4(bf[nt2],
                      kb + ((warp_n * 64 + nt2 * 16 + brow) * P1_LDH + s * 16 + bcolh) * 2);
#pragma unroll
            for (int nt2 = 0; nt2 < 4; ++nt2)
#pragma unroll
                for (int mt = 0; mt < 2; ++mt) {
                    mma16(acc[mt][2 * nt2],     a[mt], bf[nt2][0], bf[nt2][1]);
                    mma16(acc[mt][2 * nt2 + 1], a[mt], bf[nt2][2], bf[nt2][3]);
                }
        }
    }
    __syncthreads();

    // store S (scaled) fp32
#pragma unroll
    for (int mt = 0; mt < 2; ++mt)
#pragma unroll
        for (int nt = 0; nt < 8; ++nt) {
            int r = warp_m * 32 + mt * 16 + grp;
            int c = warp_n * 64 + nt * 8 + 2 * qd;
            sS[r * SS_LD + c]           = acc[mt][nt][0] * SCALE;
            sS[r * SS_LD + c + 1]       = acc[mt][nt][1] * SCALE;
            sS[(r + 8) * SS_LD + c]     = acc[mt][nt][2] * SCALE;
            sS[(r + 8) * SS_LD + c + 1] = acc[mt][nt][3] * SCALE;
        }
    __syncthreads();

    // ---------- softmax (8 warps x 8 rows); probs -> fp16 sP ----------
#pragma unroll
    for (int r = 0; r < 8; ++r) {
        int q = wid * 8 + r;
        float* row = sS + q * SS_LD;
        __half* rowp = sP + q * PS_LDH;
        float v[8];
        float mx = -1e30f;
#pragma unroll
        for (int m = 0; m < 8; ++m) {
            v[m] = row[lane + 32 * m];
            mx = fmaxf(mx, v[m]);
        }
#pragma unroll
        for (int s = 16; s > 0; s >>= 1)
            mx = fmaxf(mx, __shfl_xor_sync(0xffffffffu, mx, s));
        float sum = 0.0f;
#pragma unroll
        for (int m = 0; m < 8; ++m) {
            v[m] = __expf(v[m] - mx);
            sum += v[m];
        }
#pragma unroll
        for (int s = 16; s > 0; s >>= 1)
            sum += __shfl_xor_sync(0xffffffffu, sum, s);
        float inv = 1.0f / sum;
#pragma unroll
        for (int m = 0; m < 8; ++m)
            rowp[lane + 32 * m] = __float2half_rn(v[m] * inv);
    }
    __syncthreads();

    // ---------- P fragments: full k=256 register-resident ----------
    const int warp_m2 = wid & 3;
    const int warp_n2 = wid >> 2;

    uint32_t aP[16][4];
#pragma unroll
    for (int ks = 0; ks < 16; ++ks)
        ldsm4(aP[ks], sb + ((warp_m2 * 16 + lrow) * PS_LDH + ks * 16 + lcolh) * 2);
    __syncthreads();

    // ---------- Phase 2: O^T in 12 c-chunks of 64; n-split ----------
    const int tkrow = (lane & 7) + ((lane >> 3) & 1) * 8;
    const int tnblk = (lane >> 4) * 8;

    auto load_k2 = [&](int it, int st) {
        int c0 = it * 64;
        uint32_t kb = sb + st * 36864;
#pragma unroll
        for (int p = 0; p < 8; ++p) {
            int id = p * 256 + tid;
            int row = id >> 3, cc = (id & 7) * 8;
            cpa16(kb + row * 144 + cc * 2, xhK + row * CDIM + c0 + cc);
        }
        cpa_commit();
    };

    load_k2(0, 0);
    for (int it = 0; it < 12; ++it) {
        int c0 = it * 64;
        cpa_wait<0>();
        __syncthreads();
        if (it + 1 < 12) load_k2(it + 1, (it + 1) & 1);

        uint32_t kb = sb + (it & 1) * 36864;

        float acc2[4][4];
#pragma unroll
        for (int i = 0; i < 4; ++i)
#pragma unroll
            for (int r = 0; r < 4; ++r) acc2[i][r] = 0.0f;

#pragma unroll
        for (int ks = 0; ks < 16; ++ks) {
            int kbase = ks * 16;
            uint32_t bt[2][4];
#pragma unroll
            for (int h = 0; h < 2; ++h)
                ldsm4t(bt[h], kb + ((kbase + tkrow) * K2_LDH +
                                    warp_n2 * 32 + h * 16 + tnblk) * 2);
            mma16(acc2[0], aP[ks], bt[0][0], bt[0][1]);
            mma16(acc2[1], aP[ks], bt[0][2], bt[0][3]);
            mma16(acc2[2], aP[ks], bt[1][0], bt[1][1]);
            mma16(acc2[3], aP[ks], bt[1][2], bt[1][3]);
        }

        // stage transposed [c_local][t]
#pragma unroll
        for (int nt = 0; nt < 4; ++nt) {
            int cc = warp_n2 * 32 + nt * 8 + 2 * qd;
            int rq = warp_m2 * 16 + grp;
            stage[cc * STG_LD + rq]           = acc2[nt][0];
            stage[(cc + 1) * STG_LD + rq]     = acc2[nt][1];
            stage[cc * STG_LD + rq + 8]       = acc2[nt][2];
            stage[(cc + 1) * STG_LD + rq + 8] = acc2[nt][3];
        }
        __syncthreads();

        // convert to fp16, write 64x64 O^T chunk (coalesced)
#pragma unroll
        for (int p = 0; p < 2; ++p) {
            int id = p * 256 + tid;
            int row = id >> 3, c8 = (id & 7) * 8;
            float4 a = *(float4*)&stage[row * STG_LD + c8];
            float4 c = *(float4*)&stage[row * STG_LD + c8 + 4];
            uint2 ha = f4h(a), hb = f4h(c);
            uint4 pk = make_uint4(ha.x, ha.y, hb.x, hb.y);
            *(uint4*)(g_OTh + (size_t)b * CDIM * LZ + (size_t)(c0 + row) * LZ + c8) = pk;
        }
        __syncthreads();
    }
}

// ---------------- projection: Y_all(16384x768)h @ Wh^T + bias ----------------
#define PJ_LDH 40
#define PJ_STAGE_B 20480
#define PJ_SMEM (3 * PJ_STAGE_B)

extern __shared__ char psmemc[];

__global__ __launch_bounds__(256, 2) void proj_k(const float* __restrict__ bias,
                                                 float* __restrict__ out) {
    const int o0 = blockIdx.x * 128;
    const int m0 = blockIdx.y * 128;
    const int tid  = threadIdx.x;
    const int wid  = tid >> 5;
    const int lane = tid & 31;
    const int grp  = lane >> 2;
    const int qd   = lane & 3;
    const int warp_m = wid >> 2;
    const int warp_n = wid & 3;

    uint32_t pb;
    asm("{ .reg .u64 t; cvta.to.shared.u64 t, %1; cvt.u32.u64 %0, t; }"
        : "=r"(pb) : "l"(psmemc));

    const int lrow  = lane & 15;
    const int lcolh = (lane >> 4) * 8;
    const int brow  = (lane & 7) + ((lane >> 4) << 3);
    const int bcolh = ((lane >> 3) & 1) * 8;

    float acc[4][4][4];
#pragma unroll
    for (int i = 0; i < 4; ++i)
#pragma unroll
        for (int j = 0; j < 4; ++j)
#pragma unroll
            for (int r = 0; r < 4; ++r) acc[i][j][r] = 0.0f;

    auto load_tiles = [&](int it, int st) {
        int k0 = it * 32;
        uint32_t ab = pb + st * PJ_STAGE_B;
        uint32_t bb = ab + 10240;
#pragma unroll
        for (int p = 0; p < 2; ++p) {
            int id = p * 256 + tid;
            int row = id >> 2, kc = (id & 3) * 8;
            cpa16(ab + row * 80 + kc * 2, g_OTh + (size_t)(m0 + row) * CDIM + k0 + kc);
        }
#pragma unroll
        for (int p = 0; p < 2; ++p) {
            int id = p * 256 + tid;
            int row = id >> 2, kc = (id & 3) * 8;
            cpa16(bb + row * 80 + kc * 2, g_Wh + (size_t)(o0 + row) * CDIM + k0 + kc);
        }
        cpa_commit();
    };

    load_tiles(0, 0);
    load_tiles(1, 1);
    for (int it = 0; it < 24; ++it) {
        if (it == 23) cpa_wait<0>(); else cpa_wait<1>();
        __syncthreads();
        if (it + 2 < 24) load_tiles(it + 2, (it + 2) % 3);

        uint32_t ab = pb + (it % 3) * PJ_STAGE_B;
        uint32_t bb = ab + 10240;
#pragma unroll
        for (int s = 0; s < 2; ++s) {
            uint32_t a[4][4], bf[2][4];
            ldsm4(bf[0], bb + ((warp_n * 32 + brow) * PJ_LDH + s * 16 + bcolh) * 2);
            ldsm4(bf[1], bb + ((warp_n * 32 + 16 + brow) * PJ_LDH + s * 16 + bcolh) * 2);
#pragma unroll
            for (int mt = 0; mt < 4; ++mt)
                ldsm4(a[mt],
                      ab + ((warp_m * 64 + mt * 16 + lrow) * PJ_LDH + s * 16 + lcolh) * 2);
#pragma unroll
            for (int mt = 0; mt < 4; ++mt)
#pragma unroll
                for (int p = 0; p < 2; ++p) {
                    mma16(acc[mt][2 * p],     a[mt], bf[p][0], bf[p][1]);
                    mma16(acc[mt][2 * p + 1], a[mt], bf[p][2], bf[p][3]);
                }
        }
    }

    // epilogue: bias + store (row -> (b, q))
#pragma unroll
    for (int mt = 0; mt < 4; ++mt)
#pragma unroll
        for (int nt = 0; nt < 4; ++nt) {
            int gr = m0 + warp_m * 64 + mt * 16 + grp;
            int o  = o0 + warp_n * 32 + nt * 8 + 2 * qd;
            float bv0 = bias[o], bv1 = bias[o + 1];
            int b0i = gr >> 6, q0 = gr & 63;
            int b1i = (gr + 8) >> 6, q1 = (gr + 8) & 63;
            float2 v0 = make_float2(acc[mt][nt][0] + bv0, acc[mt][nt][1] + bv1);
            float2 v1 = make_float2(acc[mt][nt][2] + bv0, acc[mt][nt][3] + bv1);
            *(float2*)&out[(size_t)b0i * NTOK * CDIM + (size_t)q0 * CDIM + o] = v0;
            *(float2*)&out[(size_t)b1i * NTOK * CDIM + (size_t)q1 * CDIM + o] = v1;
        }
}

extern "C" void kernel_launch(void* const* d_in, const int* in_sizes, int n_in,
                              void* d_out, int out_size) {
    const float* x    = (const float*)d_in[0];
    const float* w    = (const float*)d_in[1];
    const float* bias = (const float*)d_in[2];
    float* out = (float*)d_out;

    // lazily created on the FIRST (non-capture) correctness call; reused in capture
    static cudaStream_t s2 = nullptr;
    static cudaEvent_t ev_fork = nullptr, ev_join = nullptr;
    if (s2 == nullptr) {
        cudaStreamCreateWithFlags(&s2, cudaStreamNonBlocking);
        cudaEventCreateWithFlags(&ev_fork, cudaEventDisableTiming);
        cudaEventCreateWithFlags(&ev_join, cudaEventDisableTiming);
    }

    // fork: tail copy runs concurrently on s2
    cudaEventRecord(ev_fork, 0);
    cudaStreamWaitEvent(s2, ev_fork, 0);
    copy_tail<<<2048, 256, 0, s2>>>((const float4*)x, (float4*)out);
    cudaEventRecord(ev_join, s2);

    // main chain on stream 0
    conv_k<<<2048, 256>>>((const float4*)x, (const float4*)w);

    cudaFuncSetAttribute(attn_k, cudaFuncAttributeMaxDynamicSharedMemorySize, AT_SMEM);
    attn_k<<<BATCH, 256, AT_SMEM>>>();

    cudaFuncSetAttribute(proj_k, cudaFuncAttributeMaxDynamicSharedMemorySize, PJ_SMEM);
    proj_k<<<dim3(6, 128), 256, PJ_SMEM>>>(bias, out);

    // join
    cudaStreamWaitEvent(0, ev_join, 0);
}

// round 16
// speedup vs baseline: 1.1249x; 1.1249x over previous
#include <cuda_runtime.h>
#include <cuda_fp16.h>
#include <cstdint>

#define BATCH 256
#define NTOK  320
#define CDIM  768
#define LZ    64
#define LK    256
#define SCALE 0.125f

__device__ __half g_Xh[(size_t)BATCH * NTOK * CDIM];   // fp16 copy of x
__device__ __half g_Wh[(size_t)CDIM * CDIM];           // fp16 copy of proj_w
__device__ __half g_OTh[(size_t)BATCH * CDIM * LZ];    // O^T fp16; flat == Y_all(16384x768)

__device__ __forceinline__ void mma16(float* d, const uint32_t* a,
                                      uint32_t b0, uint32_t b1) {
    asm volatile(
        "mma.sync.aligned.m16n8k16.row.col.f32.f16.f16.f32 "
        "{%0,%1,%2,%3}, {%4,%5,%6,%7}, {%8,%9}, {%0,%1,%2,%3};\n"
        : "+f"(d[0]), "+f"(d[1]), "+f"(d[2]), "+f"(d[3])
        : "r"(a[0]), "r"(a[1]), "r"(a[2]), "r"(a[3]), "r"(b0), "r"(b1));
}
__device__ __forceinline__ void ldsm4(uint32_t* r, uint32_t saddr) {
    asm volatile("ldmatrix.sync.aligned.m8n8.x4.shared.b16 {%0,%1,%2,%3}, [%4];"
                 : "=r"(r[0]), "=r"(r[1]), "=r"(r[2]), "=r"(r[3]) : "r"(saddr));
}
__device__ __forceinline__ void ldsm4t(uint32_t* r, uint32_t saddr) {
    asm volatile("ldmatrix.sync.aligned.m8n8.x4.trans.shared.b16 {%0,%1,%2,%3}, [%4];"
                 : "=r"(r[0]), "=r"(r[1]), "=r"(r[2]), "=r"(r[3]) : "r"(saddr));
}
__device__ __forceinline__ void cpa16(uint32_t saddr, const void* gaddr) {
    asm volatile("cp.async.cg.shared.global [%0], [%1], 16;\n"
                 :: "r"(saddr), "l"(gaddr));
}
__device__ __forceinline__ void cpa_commit() {
    asm volatile("cp.async.commit_group;\n");
}
template <int N>
__device__ __forceinline__ void cpa_wait() {
    asm volatile("cp.async.wait_group %0;\n" :: "n"(N));
}

__device__ __forceinline__ uint2 f4h(float4 v) {
    __half2 a = __floats2half2_rn(v.x, v.y);
    __half2 b = __floats2half2_rn(v.z, v.w);
    uint2 r;
    r.x = *(uint32_t*)&a;
    r.y = *(uint32_t*)&b;
    return r;
}

// ---------------- convert pass: x->fp16, W->fp16, exact fp32 tail copy ----------------
__global__ void conv_k(const float4* __restrict__ x4, const float4* __restrict__ w4,
                       float4* __restrict__ o4) {
    const int WCH = CDIM * CDIM / 4;
    const int XCH = BATCH * NTOK * CDIM / 4;
    uint2* xh2 = (uint2*)g_Xh;
    uint2* wh2 = (uint2*)g_Wh;
    for (long i = blockIdx.x * blockDim.x + threadIdx.x; i < WCH + XCH;
         i += (long)gridDim.x * blockDim.x) {
        if (i < WCH) {
            wh2[i] = f4h(w4[i]);
        } else {
            long j = i - WCH;
            float4 v = x4[j];
            xh2[j] = f4h(v);
            int tok = (int)((j / 192) % 320);
            if (tok >= LZ) o4[j] = v;   // exact concat tail
        }
    }
}

// ---------------- fused attention per batch (fp16 tensor cores) ----------------
#define P1_LDH 40    // halves; 80B row => conflict-free ldsm
#define SS_LD  260   // fp32 words
#define PS_LDH 264   // halves
#define K2_LDH 72    // halves; 144B row => conflict-free ldsm4t
#define STG_LD 68    // fp32 words

// layout: phase1 3 x 25600B [0,76800) (time-muxed with sP/sS below)
//         sP halves [0,33792); sS fp32 [34048,100608)
//         phase2: K2 2 x 36864 [0,73728); stage 64x68x4 [73728,91136)
#define AT_SMEM 100608

extern __shared__ char smemc[];

__global__ __launch_bounds__(256, 2) void attn_k() {
    float*  sS = (float*)(smemc + 34048);
    __half* sP = (__half*)smemc;
    float*  stage = (float*)(smemc + 73728);
    uint32_t sb;
    asm("{ .reg .u64 t; cvta.to.shared.u64 t, %1; cvt.u32.u64 %0, t; }"
        : "=r"(sb) : "l"(smemc));

    const int b    = blockIdx.x;
    const int tid  = threadIdx.x;
    const int wid  = tid >> 5;
    const int lane = tid & 31;
    const int grp  = lane >> 2;
    const int qd   = lane & 3;
    const __half* xhb = g_Xh + (size_t)b * NTOK * CDIM;
    const __half* xhK = xhb + LZ * CDIM;

    const int lrow  = lane & 15;
    const int lcolh = (lane >> 4) * 8;
    const int brow  = (lane & 7) + ((lane >> 4) << 3);
    const int bcolh = ((lane >> 3) & 1) * 8;

    // ---------- Phase 1: S = Q K^T * scale (3-stage cp.async) ----------
    const int warp_m = wid >> 2;
    const int warp_n = wid & 3;

    float acc[2][8][4];
#pragma unroll
    for (int i = 0; i < 2; ++i)
#pragma unroll
        for (int j = 0; j < 8; ++j)
#pragma unroll
            for (int r = 0; r < 4; ++r) acc[i][j][r] = 0.0f;

    auto load_tiles = [&](int it, int st) {
        int c0 = it * 32;
        uint32_t qb = sb + st * 25600;
        uint32_t kb = qb + 5120;
        {
            int row = tid >> 2, kc = (tid & 3) * 8;
            cpa16(qb + row * 80 + kc * 2, xhb + row * CDIM + c0 + kc);
        }
#pragma unroll
        for (int p = 0; p < 4; ++p) {
            int id = p * 256 + tid;
            int row = id >> 2, kc = (id & 3) * 8;
            cpa16(kb + row * 80 + kc * 2, xhK + row * CDIM + c0 + kc);
        }
        cpa_commit();
    };

    load_tiles(0, 0);
    load_tiles(1, 1);
    for (int it = 0; it < 24; ++it) {
        if (it == 23) cpa_wait<0>(); else cpa_wait<1>();
        __syncthreads();
        if (it + 2 < 24) load_tiles(it + 2, (it + 2) % 3);

        uint32_t qb = sb + (it % 3) * 25600;
        uint32_t kb = qb + 5120;
#pragma unroll
        for (int s = 0; s < 2; ++s) {
            uint32_t a[2][4], bf[4][4];
            ldsm4(a[0], qb + ((warp_m * 32 + lrow) * P1_LDH + s * 16 + lcolh) * 2);
            ldsm4(a[1], qb + ((warp_m * 32 + 16 + lrow) * P1_LDH + s * 16 + lcolh) * 2);
#pragma unroll
            for (int nt2 = 0; nt2 < 4; ++nt2)
                ldsm4(bf[nt2],
                      kb + ((warp_n * 64 + nt2 * 16 + brow) * P1_LDH + s * 16 + bcolh) * 2);
#pragma unroll
            for (int nt2 = 0; nt2 < 4; ++nt2)
#pragma unroll
                for (int mt = 0; mt < 2; ++mt) {
                    mma16(acc[mt][2 * nt2],     a[mt], bf[nt2][0], bf[nt2][1]);
                    mma16(acc[mt][2 * nt2 + 1], a[mt], bf[nt2][2], bf[nt2][3]);
                }
        }
    }
    __syncthreads();

    // store S (scaled) fp32
#pragma unroll
    for (int mt = 0; mt < 2; ++mt)
#pragma unroll
        for (int nt = 0; nt < 8; ++nt) {
            int r = warp_m * 32 + mt * 16 + grp;
            int c = warp_n * 64 + nt * 8 + 2 * qd;
            sS[r * SS_LD + c]           = acc[mt][nt][0] * SCALE;
            sS[r * SS_LD + c + 1]       = acc[mt][nt][1] * SCALE;
            sS[(r + 8) * SS_LD + c]     = acc[mt][nt][2] * SCALE;
            sS[(r + 8) * SS_LD + c + 1] = acc[mt][nt][3] * SCALE;
        }
    __syncthreads();

    // ---------- softmax (8 warps x 8 rows); probs -> fp16 sP ----------
#pragma unroll
    for (int r = 0; r < 8; ++r) {
        int q = wid * 8 + r;
        float* row = sS + q * SS_LD;
        __half* rowp = sP + q * PS_LDH;
        float v[8];
        float mx = -1e30f;
#pragma unroll
        for (int m = 0; m < 8; ++m) {
            v[m] = row[lane + 32 * m];
            mx = fmaxf(mx, v[m]);
        }
#pragma unroll
        for (int s = 16; s > 0; s >>= 1)
            mx = fmaxf(mx, __shfl_xor_sync(0xffffffffu, mx, s));
        float sum = 0.0f;
#pragma unroll
        for (int m = 0; m < 8; ++m) {
            v[m] = __expf(v[m] - mx);
            sum += v[m];
        }
#pragma unroll
        for (int s = 16; s > 0; s >>= 1)
            sum += __shfl_xor_sync(0xffffffffu, sum, s);
        float inv = 1.0f / sum;
#pragma unroll
        for (int m = 0; m < 8; ++m)
            rowp[lane + 32 * m] = __float2half_rn(v[m] * inv);
    }
    __syncthreads();

    // ---------- P fragments: full k=256 register-resident ----------
    const int warp_m2 = wid & 3;
    const int warp_n2 = wid >> 2;

    uint32_t aP[16][4];
#pragma unroll
    for (int ks = 0; ks < 16; ++ks)
        ldsm4(aP[ks], sb + ((warp_m2 * 16 + lrow) * PS_LDH + ks * 16 + lcolh) * 2);
    __syncthreads();

    // ---------- Phase 2: O^T in 12 c-chunks of 64; n-split ----------
    const int tkrow = (lane & 7) + ((lane >> 3) & 1) * 8;
    const int tnblk = (lane >> 4) * 8;

    auto load_k2 = [&](int it, int st) {
        int c0 = it * 64;
        uint32_t kb = sb + st * 36864;
#pragma unroll
        for (int p = 0; p < 8; ++p) {
            int id = p * 256 + tid;
            int row = id >> 3, cc = (id & 7) * 8;
            cpa16(kb + row * 144 + cc * 2, xhK + row * CDIM + c0 + cc);
        }
        cpa_commit();
    };

    load_k2(0, 0);
    for (int it = 0; it < 12; ++it) {
        int c0 = it * 64;
        cpa_wait<0>();
        __syncthreads();
        if (it + 1 < 12) load_k2(it + 1, (it + 1) & 1);

        uint32_t kb = sb + (it & 1) * 36864;

        float acc2[4][4];
#pragma unroll
        for (int i = 0; i < 4; ++i)
#pragma unroll
            for (int r = 0; r < 4; ++r) acc2[i][r] = 0.0f;

#pragma unroll
        for (int ks = 0; ks < 16; ++ks) {
            int kbase = ks * 16;
            uint32_t bt[2][4];
#pragma unroll
            for (int h = 0; h < 2; ++h)
                ldsm4t(bt[h], kb + ((kbase + tkrow) * K2_LDH +
                                    warp_n2 * 32 + h * 16 + tnblk) * 2);
            mma16(acc2[0], aP[ks], bt[0][0], bt[0][1]);
            mma16(acc2[1], aP[ks], bt[0][2], bt[0][3]);
            mma16(acc2[2], aP[ks], bt[1][0], bt[1][1]);
            mma16(acc2[3], aP[ks], bt[1][2], bt[1][3]);
        }

        // stage transposed [c_local][t]
#pragma unroll
        for (int nt = 0; nt < 4; ++nt) {
            int cc = warp_n2 * 32 + nt * 8 + 2 * qd;
            int rq = warp_m2 * 16 + grp;
            stage[cc * STG_LD + rq]           = acc2[nt][0];
            stage[(cc + 1) * STG_LD + rq]     = acc2[nt][1];
            stage[cc * STG_LD + rq + 8]       = acc2[nt][2];
            stage[(cc + 1) * STG_LD + rq + 8] = acc2[nt][3];
        }
        __syncthreads();

        // convert to fp16, write 64x64 O^T chunk (coalesced)
#pragma unroll
        for (int p = 0; p < 2; ++p) {
            int id = p * 256 + tid;
            int row = id >> 3, c8 = (id & 7) * 8;
            float4 a = *(float4*)&stage[row * STG_LD + c8];
            float4 c = *(float4*)&stage[row * STG_LD + c8 + 4];
            uint2 ha = f4h(a), hb = f4h(c);
            uint4 pk = make_uint4(ha.x, ha.y, hb.x, hb.y);
            *(uint4*)(g_OTh + (size_t)b * CDIM * LZ + (size_t)(c0 + row) * LZ + c8) = pk;
        }
        __syncthreads();
    }
}

// ---------------- projection: Y_all(16384x768)h @ Wh^T + bias ----------------
#define PJ_LDH 40
#define PJ_STAGE_B 20480
#define PJ_SMEM (3 * PJ_STAGE_B)

extern __shared__ char psmemc[];

__global__ __launch_bounds__(256, 2) void proj_k(const float* __restrict__ bias,
                                                 float* __restrict__ out) {
    const int o0 = blockIdx.x * 128;
    const int m0 = blockIdx.y * 128;
    const int tid  = threadIdx.x;
    const int wid  = tid >> 5;
    const int lane = tid & 31;
    const int grp  = lane >> 2;
    const int qd   = lane & 3;
    const int warp_m = wid >> 2;
    const int warp_n = wid & 3;

    uint32_t pb;
    asm("{ .reg .u64 t; cvta.to.shared.u64 t, %1; cvt.u32.u64 %0, t; }"
        : "=r"(pb) : "l"(psmemc));

    const int lrow  = lane & 15;
    const int lcolh = (lane >> 4) * 8;
    const int brow  = (lane & 7) + ((lane >> 4) << 3);
    const int bcolh = ((lane >> 3) & 1) * 8;

    float acc[4][4][4];
#pragma unroll
    for (int i = 0; i < 4; ++i)
#pragma unroll
        for (int j = 0; j < 4; ++j)
#pragma unroll
            for (int r = 0; r < 4; ++r) acc[i][j][r] = 0.0f;

    auto load_tiles = [&](int it, int st) {
        int k0 = it * 32;
        uint32_t ab = pb + st * PJ_STAGE_B;
        uint32_t bb = ab + 10240;
#pragma unroll
        for (int p = 0; p < 2; ++p) {
            int id = p * 256 + tid;
            int row = id >> 2, kc = (id & 3) * 8;
            cpa16(ab + row * 80 + kc * 2, g_OTh + (size_t)(m0 + row) * CDIM + k0 + kc);
        }
#pragma unroll
        for (int p = 0; p < 2; ++p) {
            int id = p * 256 + tid;
            int row = id >> 2, kc = (id & 3) * 8;
            cpa16(bb + row * 80 + kc * 2, g_Wh + (size_t)(o0 + row) * CDIM + k0 + kc);
        }
        cpa_commit();
    };

    load_tiles(0, 0);
    load_tiles(1, 1);
    for (int it = 0; it < 24; ++it) {
        if (it == 23) cpa_wait<0>(); else cpa_wait<1>();
        __syncthreads();
        if (it + 2 < 24) load_tiles(it + 2, (it + 2) % 3);

        uint32_t ab = pb + (it % 3) * PJ_STAGE_B;
        uint32_t bb = ab + 10240;
#pragma unroll
        for (int s = 0; s < 2; ++s) {
            uint32_t a[4][4], bf[2][4];
            ldsm4(bf[0], bb + ((warp_n * 32 + brow) * PJ_LDH + s * 16 + bcolh) * 2);
            ldsm4(bf[1], bb + ((warp_n * 32 + 16 + brow) * PJ_LDH + s * 16 + bcolh) * 2);
#pragma unroll
            for (int mt = 0; mt < 4; ++mt)
                ldsm4(a[mt],
                      ab + ((warp_m * 64 + mt * 16 + lrow) * PJ_LDH + s * 16 + lcolh) * 2);
#pragma unroll
            for (int mt = 0; mt < 4; ++mt)
#pragma unroll
                for (int p = 0; p < 2; ++p) {
                    mma16(acc[mt][2 * p],     a[mt], bf[p][0], bf[p][1]);
                    mma16(acc[mt][2 * p + 1], a[mt], bf[p][2], bf[p][3]);
                }
        }
    }

    // epilogue: bias + store (row -> (b, q))
#pragma unroll
    for (int mt = 0; mt < 4; ++mt)
#pragma unroll
        for (int nt = 0; nt < 4; ++nt) {
            int gr = m0 + warp_m * 64 + mt * 16 + grp;
            int o  = o0 + warp_n * 32 + nt * 8 + 2 * qd;
            float bv0 = bias[o], bv1 = bias[o + 1];
            int b0i = gr >> 6, q0 = gr & 63;
            int b1i = (gr + 8) >> 6, q1 = (gr + 8) & 63;
            float2 v0 = make_float2(acc[mt][nt][0] + bv0, acc[mt][nt][1] + bv1);
            float2 v1 = make_float2(acc[mt][nt][2] + bv0, acc[mt][nt][3] + bv1);
            *(float2*)&out[(size_t)b0i * NTOK * CDIM + (size_t)q0 * CDIM + o] = v0;
            *(float2*)&out[(size_t)b1i * NTOK * CDIM + (size_t)q1 * CDIM + o] = v1;
        }
}

extern "C" void kernel_launch(void* const* d_in, const int* in_sizes, int n_in,
                              void* d_out, int out_size) {
    const float* x    = (const float*)d_in[0];
    const float* w    = (const float*)d_in[1];
    const float* bias = (const float*)d_in[2];
    float* out = (float*)d_out;

    conv_k<<<2048, 256>>>((const float4*)x, (const float4*)w, (float4*)out);

    cudaFuncSetAttribute(attn_k, cudaFuncAttributeMaxDynamicSharedMemorySize, AT_SMEM);
    attn_k<<<BATCH, 256, AT_SMEM>>>();

    cudaFuncSetAttribute(proj_k, cudaFuncAttributeMaxDynamicSharedMemorySize, PJ_SMEM);
    proj_k<<<dim3(6, 128), 256, PJ_SMEM>>>(bias, out);
}